// round 13
// baseline (speedup 1.0000x reference)
#include <cuda_runtime.h>
#include <cstdint>

#define NN 50000
#define EE 800000
#define DD 64
#define HH 4
#define FF 128
#define LL 2

#define ASTR 68
#define B2STR 68   // float2 units per B row (136 words; 136%32==8 -> conflict-free)

// ---------------- device scratch (static, no allocation) ----------------
__device__ float g_Q[NN*DD];
__device__ float g_K[NN*DD];
__device__ float g_V[NN*DD];
__device__ float g_wV[NN*DD];
__device__ float g_Z[NN*HH];
__device__ float g_h[NN*DD];    // inter-layer h
__device__ float g_h1[NN*DD];   // post-LN1
__device__ float g_u[NN*FF];    // FFN hidden
__device__ int2  g_eidx[EE];    // packed (src,dst) int32
__device__ int   g_is64;

// ---------------- tf32 helpers ----------------
__device__ __forceinline__ void split_tf32(float x, uint32_t& hi, uint32_t& lo){
    asm("cvt.rna.tf32.f32 %0, %1;" : "=r"(hi) : "f"(x));
    float r = x - __uint_as_float(hi);
    asm("cvt.rna.tf32.f32 %0, %1;" : "=r"(lo) : "f"(r));
}
__device__ __forceinline__ void mma8(float* c, const uint32_t* a, uint32_t b0, uint32_t b1){
    asm volatile(
      "mma.sync.aligned.m16n8k8.row.col.f32.tf32.tf32.f32 "
      "{%0,%1,%2,%3}, {%4,%5,%6,%7}, {%8,%9}, {%0,%1,%2,%3};"
      : "+f"(c[0]), "+f"(c[1]), "+f"(c[2]), "+f"(c[3])
      : "r"(a[0]), "r"(a[1]), "r"(a[2]), "r"(a[3]), "r"(b0), "r"(b1));
}

// ---------------- index dtype detection (int64 vs int32) ----------------
__global__ void detect_idx_kernel(const long long* __restrict__ idx){
    if (blockIdx.x == 0 && threadIdx.x == 0){
        int ok = 1;
        #pragma unroll
        for (int i = 0; i < 16; i++){
            long long v = idx[i];
            if (v < 0 || v >= NN) ok = 0;
        }
        g_is64 = ok;
    }
}

// ---------------- index conversion to packed int2 (once per launch) ------
__global__ void convert_idx_kernel(const void* __restrict__ eidx){
    int e = blockIdx.x * 256 + threadIdx.x;
    if (e < EE){
        int s, d;
        if (g_is64){
            const long long* p = (const long long*)eidx;
            s = (int)p[e]; d = (int)p[EE + e];
        } else {
            const int* p = (const int*)eidx;
            s = p[e]; d = p[EE + e];
        }
        g_eidx[e] = make_int2(s, d);
    }
}

// ---------------- zero accumulators (vectorized) ----------------
__global__ void zero_kernel(){
    int i = blockIdx.x * blockDim.x + threadIdx.x;
    if (i < NN*DD/4) ((float4*)g_wV)[i] = make_float4(0.f,0.f,0.f,0.f);
    if (i < NN*HH/4) ((float4*)g_Z)[i]  = make_float4(0.f,0.f,0.f,0.f);
}

// ================= MMA tile compute: [128,64]@[64,64], 3xTF32 ============
// B in smem as float2{hi,lo} rows (stride B2STR). Accumulates into c.
__device__ __forceinline__ void gemm_tile_acc(
        const float* sA, const float2* sB2,
        int warp, int lane, float c[8][4]){
    const int gID = lane >> 2, tig = lane & 3;
    const int wr = warp * 16;
    #pragma unroll
    for (int k = 0; k < 8; k++){
        const float* ap = sA + (wr + gID)*ASTR + k*8 + tig;
        float a0f = ap[0], a1f = ap[8*ASTR], a2f = ap[4], a3f = ap[8*ASTR + 4];
        uint32_t ah[4], al[4];
        split_tf32(a0f, ah[0], al[0]);
        split_tf32(a1f, ah[1], al[1]);
        split_tf32(a2f, ah[2], al[2]);
        split_tf32(a3f, ah[3], al[3]);
        const int brow = k*8 + tig;
        #pragma unroll
        for (int nt = 0; nt < 8; nt++){
            const int bc = nt*8 + gID;
            float2 b0 = sB2[brow*B2STR + bc];        // {hi, lo} @ row brow
            float2 b1 = sB2[(brow+4)*B2STR + bc];    // {hi, lo} @ row brow+4
            mma8(c[nt], ah, __float_as_uint(b0.x), __float_as_uint(b1.x)); // hi*hi
            mma8(c[nt], ah, __float_as_uint(b0.y), __float_as_uint(b1.y)); // hi*lo
            mma8(c[nt], al, __float_as_uint(b0.x), __float_as_uint(b1.x)); // lo*hi
        }
    }
}
__device__ __forceinline__ void zero_c(float c[8][4]){
    #pragma unroll
    for (int nt = 0; nt < 8; nt++){ c[nt][0]=c[nt][1]=c[nt][2]=c[nt][3]=0.f; }
}

__device__ __forceinline__ void gemm_store(
        float* __restrict__ C, int m0, int M, int warp, int lane, float c[8][4]){
    const int gID = lane >> 2, tig = lane & 3;
    const int r0 = m0 + warp*16 + gID;
    const int r1 = r0 + 8;
    #pragma unroll
    for (int nt = 0; nt < 8; nt++){
        const int col = nt*8 + tig*2;
        if (r0 < M) *(float2*)&C[(size_t)r0*DD + col] = make_float2(c[nt][0], c[nt][1]);
        if (r1 < M) *(float2*)&C[(size_t)r1*DD + col] = make_float2(c[nt][2], c[nt][3]);
    }
}

// stage B (64x64) as packed float2{hi,lo} into smem
__device__ __forceinline__ void stage_B2(const float* __restrict__ B,
                                         float2* sB2, int tid, int nthreads){
    for (int i = tid; i < 64*64; i += nthreads){
        int r = i >> 6, cc = i & 63;
        uint32_t h, l; split_tf32(B[i], h, l);
        sB2[r*B2STR + cc] = make_float2(__uint_as_float(h), __uint_as_float(l));
    }
}

// register-resident LN epilogue over 64-col rows spread across a lane-quad
__device__ __forceinline__ void ln_epilogue(
        float c[8][4], int m0, int warp, int lane,
        const float* __restrict__ resid, const float* __restrict__ bias,
        const float* __restrict__ lg, const float* __restrict__ lb,
        float* __restrict__ out){
    const int gID = lane >> 2, tig = lane & 3;
    const int r0 = m0 + warp*16 + gID;
    const int r1 = r0 + 8;
    const int ra = (r0 < NN) ? r0 : NN-1;
    const int rb = (r1 < NN) ? r1 : NN-1;
    float s1a=0.f, s2a=0.f, s1b=0.f, s2b=0.f;
    #pragma unroll
    for (int nt = 0; nt < 8; nt++){
        const int col = nt*8 + tig*2;
        float2 bb = *(const float2*)&bias[col];
        float2 ha = *(const float2*)&resid[(size_t)ra*DD + col];
        float2 hb = *(const float2*)&resid[(size_t)rb*DD + col];
        c[nt][0] += bb.x + ha.x;  c[nt][1] += bb.y + ha.y;
        c[nt][2] += bb.x + hb.x;  c[nt][3] += bb.y + hb.y;
        s1a += c[nt][0] + c[nt][1];
        s2a += c[nt][0]*c[nt][0] + c[nt][1]*c[nt][1];
        s1b += c[nt][2] + c[nt][3];
        s2b += c[nt][2]*c[nt][2] + c[nt][3]*c[nt][3];
    }
    #pragma unroll
    for (int off = 1; off <= 2; off <<= 1){
        s1a += __shfl_xor_sync(0xffffffffu, s1a, off);
        s2a += __shfl_xor_sync(0xffffffffu, s2a, off);
        s1b += __shfl_xor_sync(0xffffffffu, s1b, off);
        s2b += __shfl_xor_sync(0xffffffffu, s2b, off);
    }
    const float mua = s1a*(1.0f/DD), vara = s2a*(1.0f/DD) - mua*mua;
    const float mub = s1b*(1.0f/DD), varb = s2b*(1.0f/DD) - mub*mub;
    const float inva = rsqrtf(vara + 1e-5f);
    const float invb = rsqrtf(varb + 1e-5f);
    #pragma unroll
    for (int nt = 0; nt < 8; nt++){
        const int col = nt*8 + tig*2;
        float2 gg = *(const float2*)&lg[col];
        float2 bb = *(const float2*)&lb[col];
        if (r0 < NN) *(float2*)&out[(size_t)r0*DD + col] =
            make_float2((c[nt][0]-mua)*inva*gg.x + bb.x,
                        (c[nt][1]-mua)*inva*gg.y + bb.y);
        if (r1 < NN) *(float2*)&out[(size_t)r1*DD + col] =
            make_float2((c[nt][2]-mub)*invb*gg.x + bb.x,
                        (c[nt][3]-mub)*invb*gg.y + bb.y);
    }
}

// common smem geometry for all 512-thread MMA kernels:
//   sA: 2 tiles x 128 x ASTR floats (69632 B), sB2: 64 x B2STR float2 (34816 B)
#define SMEM_TOTAL_BYTES (2*128*ASTR*4 + 64*B2STR*8)   // 104448

// ========== FUSED edge: 512 threads, 2x128-edge tiles ==========
__global__ void __launch_bounds__(512, 2) edge_fused_kernel(
        const float* __restrict__ A,        // edge_attr
        const float* __restrict__ B){       // WE
    extern __shared__ float sm[];
    float*  sA  = sm;                       // 2 x (128 x ASTR)
    float2* sB2 = (float2*)(sm + 2*128*ASTR);
    const int tid = threadIdx.x;
    const int m0b = blockIdx.x * 256;       // EE % 256 == 0: no tail
    for (int i = tid; i < 256*64; i += 512){
        int r = i >> 6, cc = i & 63;
        sA[(r>>7)*(128*ASTR) + (r&127)*ASTR + cc] = A[(size_t)(m0b+r)*DD + cc];
    }
    stage_B2(B, sB2, tid, 512);
    __syncthreads();
    const int warp = tid >> 5, lane = tid & 31;
    const int tileid = warp >> 3;           // 0 or 1
    const int wl = warp & 7;
    float* sAt = sA + tileid*(128*ASTR);
    float c[8][4];
    zero_c(c);
    gemm_tile_acc(sAt, sB2, wl, lane, c);
    __syncthreads();   // done reading edge_attr; safe to overwrite with Eh
    {
        const int gID = lane >> 2, tig = lane & 3;
        const int r0 = wl*16 + gID;
        const int r1 = r0 + 8;
        #pragma unroll
        for (int nt = 0; nt < 8; nt++){
            const int col = nt*8 + tig*2;
            *(float2*)&sAt[r0*ASTR + col] = make_float2(c[nt][0], c[nt][1]);
            *(float2*)&sAt[r1*ASTR + col] = make_float2(c[nt][2], c[nt][3]);
        }
    }
    __syncthreads();
    // ---- epilogue: each 256-thread half handles its tile's 128 edges ----
    const int ltid = tid & 255;
    const int t  = ltid & 15;
    const int g  = ltid >> 4;               // 0..15
    const int t4 = t * 4;
    const int m0 = m0b + tileid*128;
    int srcs[8], dsts[8];
    #pragma unroll
    for (int it = 0; it < 8; it++){
        int2 sd = g_eidx[m0 + it*16 + g];
        srcs[it] = sd.x; dsts[it] = sd.y;
    }
    #pragma unroll
    for (int it = 0; it < 8; it++){
        const int le  = it*16 + g;
        const int src = srcs[it], dst = dsts[it];
        float4 eh = *(const float4*)&sAt[le*ASTR + t4];
        float4 kk = *(const float4*)(g_K + (size_t)src*DD + t4);
        float4 qq = *(const float4*)(g_Q + (size_t)dst*DD + t4);
        float4 vv = *(const float4*)(g_V + (size_t)src*DD + t4);
        float s = kk.x*qq.x*eh.x + kk.y*qq.y*eh.y + kk.z*qq.z*eh.z + kk.w*qq.w*eh.w;
        s += __shfl_xor_sync(0xffffffffu, s, 1);
        s += __shfl_xor_sync(0xffffffffu, s, 2);
        s *= 0.25f;                        // 1/sqrt(16)
        s  = fminf(5.0f, fmaxf(-5.0f, s));
        float sc = expf(s);
        float* wb = g_wV + (size_t)dst*DD + t4;
        asm volatile("red.global.add.v4.f32 [%0], {%1, %2, %3, %4};"
                     :: "l"(wb), "f"(vv.x*sc), "f"(vv.y*sc), "f"(vv.z*sc), "f"(vv.w*sc)
                     : "memory");
        if ((t & 3) == 0){
            asm volatile("red.global.add.f32 [%0], %1;"
                         :: "l"(g_Z + (size_t)dst*HH + (t >> 2)), "f"(sc)
                         : "memory");
        }
    }
}

// ========== Q,K,V: 512 threads, 2 tiles, loop over 3 weights ==========
__global__ void __launch_bounds__(512, 2) qkv_mma_kernel(
        const float* __restrict__ A,
        const float* __restrict__ WQ, const float* __restrict__ WK,
        const float* __restrict__ WV, int M){
    extern __shared__ float sm[];
    float*  sA  = sm;
    float2* sB2 = (float2*)(sm + 2*128*ASTR);
    const int tid = threadIdx.x;
    const int m0b = blockIdx.x * 256;
    for (int i = tid; i < 256*64; i += 512){
        int r = i >> 6, cc = i & 63;
        float v = (m0b + r < M) ? A[(size_t)(m0b+r)*DD + cc] : 0.f;
        sA[(r>>7)*(128*ASTR) + (r&127)*ASTR + cc] = v;
    }
    const int warp = tid >> 5, lane = tid & 31;
    const int tileid = warp >> 3;
    const int wl = warp & 7;
    const float* sAt = sA + tileid*(128*ASTR);
    const int m0 = m0b + tileid*128;
    #pragma unroll
    for (int w = 0; w < 3; w++){
        const float* B = (w == 0) ? WQ : (w == 1) ? WK : WV;
        float* C = (w == 0) ? g_Q : (w == 1) ? g_K : g_V;
        __syncthreads();
        stage_B2(B, sB2, tid, 512);
        __syncthreads();
        float c[8][4];
        zero_c(c);
        gemm_tile_acc(sAt, sB2, wl, lane, c);
        gemm_store(C, m0, M, wl, lane, c);
    }
}

// ========== combine: 512 threads, 2 tiles, MMA + reg-LN ==========
__global__ void __launch_bounds__(512, 2) combine_mma_kernel(
        const float* __restrict__ h_in,
        const float* __restrict__ WO,
        const float* __restrict__ bO,
        const float* __restrict__ lg,
        const float* __restrict__ lb){
    extern __shared__ float sm[];
    float*  sA  = sm;
    float2* sB2 = (float2*)(sm + 2*128*ASTR);
    const int tid = threadIdx.x;
    const int m0b = blockIdx.x * 256;
    for (int i = tid; i < 256*64; i += 512){
        int r = i >> 6, cc = i & 63;
        int n = m0b + r; if (n >= NN) n = NN-1;
        float z = g_Z[n*HH + (cc >> 4)];
        sA[(r>>7)*(128*ASTR) + (r&127)*ASTR + cc] =
            g_wV[(size_t)n*DD + cc] / (z + 1e-6f);
    }
    stage_B2(WO, sB2, tid, 512);
    __syncthreads();
    const int warp = tid >> 5, lane = tid & 31;
    const int tileid = warp >> 3;
    const int wl = warp & 7;
    const float* sAt = sA + tileid*(128*ASTR);
    float c[8][4];
    zero_c(c);
    gemm_tile_acc(sAt, sB2, wl, lane, c);
    ln_epilogue(c, m0b + tileid*128, wl, lane, h_in, bO, lg, lb, g_h1);
}

// ========== FFN fc1: 512 threads, 2 tiles, two 64-col halves ==========
__global__ void __launch_bounds__(512, 2) ffn1_mma_kernel(
        const float* __restrict__ W1,
        const float* __restrict__ b1){
    extern __shared__ float sm[];
    float*  sA  = sm;
    float2* sB2 = (float2*)(sm + 2*128*ASTR);
    const int tid = threadIdx.x;
    const int m0b = blockIdx.x * 256;
    for (int i = tid; i < 256*64; i += 512){
        int r = i >> 6, cc = i & 63;
        int n = m0b + r; if (n >= NN) n = NN-1;
        sA[(r>>7)*(128*ASTR) + (r&127)*ASTR + cc] = g_h1[(size_t)n*DD + cc];
    }
    const int warp = tid >> 5, lane = tid & 31;
    const int tileid = warp >> 3;
    const int wl = warp & 7;
    const float* sAt = sA + tileid*(128*ASTR);
    const int m0 = m0b + tileid*128;
    const int gID = lane >> 2, tig = lane & 3;
    #pragma unroll
    for (int w = 0; w < 2; w++){
        __syncthreads();
        for (int i = tid; i < 64*64; i += 512){
            int r = i >> 6, cc = i & 63;
            uint32_t h, l; split_tf32(W1[r*FF + w*64 + cc], h, l);
            sB2[r*B2STR + cc] = make_float2(__uint_as_float(h), __uint_as_float(l));
        }
        __syncthreads();
        float c[8][4];
        zero_c(c);
        gemm_tile_acc(sAt, sB2, wl, lane, c);
        const int r0 = m0 + wl*16 + gID;
        const int r1 = r0 + 8;
        #pragma unroll
        for (int nt = 0; nt < 8; nt++){
            const int col = w*64 + nt*8 + tig*2;
            float2 bb = *(const float2*)&b1[col];
            if (r0 < NN) *(float2*)&g_u[(size_t)r0*FF + col] =
                make_float2(fmaxf(c[nt][0]+bb.x, 0.f), fmaxf(c[nt][1]+bb.y, 0.f));
            if (r1 < NN) *(float2*)&g_u[(size_t)r1*FF + col] =
                make_float2(fmaxf(c[nt][2]+bb.x, 0.f), fmaxf(c[nt][3]+bb.y, 0.f));
        }
    }
}

// ========== FFN fc2 + residual + LN2: 512 threads, 2 tiles, k=128 ==========
__global__ void __launch_bounds__(512, 2) ffn2_mma_kernel(
        const float* __restrict__ W2,
        const float* __restrict__ b2,
        const float* __restrict__ lg,
        const float* __restrict__ lb,
        float* __restrict__ outp){
    extern __shared__ float sm[];
    float*  sA  = sm;
    float2* sB2 = (float2*)(sm + 2*128*ASTR);
    const int tid = threadIdx.x;
    const int m0b = blockIdx.x * 256;
    const int warp = tid >> 5, lane = tid & 31;
    const int tileid = warp >> 3;
    const int wl = warp & 7;
    const float* sAt = sA + tileid*(128*ASTR);
    float c[8][4];
    zero_c(c);
    #pragma unroll
    for (int kc = 0; kc < 2; kc++){
        __syncthreads();   // protect prior chunk's smem reads
        for (int i = tid; i < 256*64; i += 512){
            int r = i >> 6, cc = i & 63;
            int n = m0b + r; if (n >= NN) n = NN-1;
            sA[(r>>7)*(128*ASTR) + (r&127)*ASTR + cc] =
                g_u[(size_t)n*FF + kc*64 + cc];
        }
        for (int i = tid; i < 64*64; i += 512){
            int r = i >> 6, cc = i & 63;
            uint32_t h, l; split_tf32(W2[(kc*64 + r)*DD + cc], h, l);
            sB2[r*B2STR + cc] = make_float2(__uint_as_float(h), __uint_as_float(l));
        }
        __syncthreads();
        gemm_tile_acc(sAt, sB2, wl, lane, c);
    }
    ln_epilogue(c, m0b + tileid*128, wl, lane, g_h1, b2, lg, lb, outp);
}

// ---------------- host launcher ----------------
extern "C" void kernel_launch(void* const* d_in, const int* in_sizes, int n_in,
                              void* d_out, int out_size){
    const float* x   = (const float*)d_in[0];
    const float* ea  = (const float*)d_in[1];
    const void*  ei  = d_in[2];
    const float* WQ  = (const float*)d_in[3];
    const float* WK  = (const float*)d_in[4];
    const float* WE  = (const float*)d_in[5];
    const float* WV  = (const float*)d_in[6];
    const float* WO  = (const float*)d_in[7];
    const float* bO  = (const float*)d_in[8];
    const float* g1  = (const float*)d_in[9];
    const float* b1n = (const float*)d_in[10];
    const float* W1  = (const float*)d_in[11];
    const float* b1  = (const float*)d_in[12];
    const float* W2  = (const float*)d_in[13];
    const float* b2  = (const float*)d_in[14];
    const float* g2  = (const float*)d_in[15];
    const float* b2n = (const float*)d_in[16];
    float* outp = (float*)d_out;

    float* p_h = nullptr;
    cudaGetSymbolAddress((void**)&p_h, g_h);

    const int big_smem = SMEM_TOTAL_BYTES;   // 104448 B
    cudaFuncSetAttribute(edge_fused_kernel,
                         cudaFuncAttributeMaxDynamicSharedMemorySize, big_smem);
    cudaFuncSetAttribute(qkv_mma_kernel,
                         cudaFuncAttributeMaxDynamicSharedMemorySize, big_smem);
    cudaFuncSetAttribute(combine_mma_kernel,
                         cudaFuncAttributeMaxDynamicSharedMemorySize, big_smem);
    cudaFuncSetAttribute(ffn1_mma_kernel,
                         cudaFuncAttributeMaxDynamicSharedMemorySize, big_smem);
    cudaFuncSetAttribute(ffn2_mma_kernel,
                         cudaFuncAttributeMaxDynamicSharedMemorySize, big_smem);

    detect_idx_kernel<<<1, 1>>>((const long long*)ei);
    convert_idx_kernel<<<(EE + 255)/256, 256>>>(ei);

    const int edge_blocks = EE / 256;           // 3125 (exact)
    const int node_blocks = (NN + 255) / 256;   // 196

    for (int l = 0; l < LL; l++){
        const float* hin  = (l == 0) ? x : (const float*)p_h;
        float*       hout = (l == LL-1) ? outp : p_h;
        zero_kernel<<<(NN*DD/4 + 255)/256, 256>>>();
        qkv_mma_kernel<<<node_blocks, 512, big_smem>>>(
            hin, WQ + l*DD*DD, WK + l*DD*DD, WV + l*DD*DD, NN);
        edge_fused_kernel<<<edge_blocks, 512, big_smem>>>(
            ea, WE + l*DD*DD);
        combine_mma_kernel<<<node_blocks, 512, big_smem>>>(
            hin, WO + l*DD*DD, bO + l*DD, g1 + l*DD, b1n + l*DD);
        ffn1_mma_kernel<<<node_blocks, 512, big_smem>>>(
            W1 + l*DD*FF, b1 + l*FF);
        ffn2_mma_kernel<<<node_blocks, 512, big_smem>>>(
            W2 + l*FF*DD, b2 + l*DD, g2 + l*DD, b2n + l*DD, hout);
    }
}

// round 14
// speedup vs baseline: 1.0973x; 1.0973x over previous
#include <cuda_runtime.h>
#include <cstdint>

#define NN 50000
#define EE 800000
#define DD 64
#define HH 4
#define FF 128
#define LL 2

#define ASTR 68
#define BSTR 72    // float stride for separate hi/lo B (node kernels)
#define B2STR 68   // float2 stride for packed B (edge kernel); 2*68 mod 32 == 8

// ---------------- device scratch (static, no allocation) ----------------
__device__ float g_Q[NN*DD];
__device__ float g_K[NN*DD];
__device__ float g_V[NN*DD];
__device__ float g_wV[NN*DD];
__device__ float g_Z[NN*HH];
__device__ float g_h[NN*DD];    // inter-layer h
__device__ float g_h1[NN*DD];   // post-LN1
__device__ float g_u[NN*FF];    // FFN hidden
__device__ int2  g_eidx[EE];    // packed (src,dst) int32
__device__ int   g_is64;

// ---------------- tf32 helpers ----------------
__device__ __forceinline__ void split_tf32(float x, uint32_t& hi, uint32_t& lo){
    asm("cvt.rna.tf32.f32 %0, %1;" : "=r"(hi) : "f"(x));
    float r = x - __uint_as_float(hi);
    asm("cvt.rna.tf32.f32 %0, %1;" : "=r"(lo) : "f"(r));
}
__device__ __forceinline__ void mma8(float* c, const uint32_t* a, uint32_t b0, uint32_t b1){
    asm volatile(
      "mma.sync.aligned.m16n8k8.row.col.f32.tf32.tf32.f32 "
      "{%0,%1,%2,%3}, {%4,%5,%6,%7}, {%8,%9}, {%0,%1,%2,%3};"
      : "+f"(c[0]), "+f"(c[1]), "+f"(c[2]), "+f"(c[3])
      : "r"(a[0]), "r"(a[1]), "r"(a[2]), "r"(a[3]), "r"(b0), "r"(b1));
}

// ---------------- index dtype detection (int64 vs int32) ----------------
__global__ void detect_idx_kernel(const long long* __restrict__ idx){
    if (blockIdx.x == 0 && threadIdx.x == 0){
        int ok = 1;
        #pragma unroll
        for (int i = 0; i < 16; i++){
            long long v = idx[i];
            if (v < 0 || v >= NN) ok = 0;
        }
        g_is64 = ok;
    }
}

// ---------------- index conversion to packed int2 (once per launch) ------
__global__ void convert_idx_kernel(const void* __restrict__ eidx){
    int e = blockIdx.x * 256 + threadIdx.x;
    if (e < EE){
        int s, d;
        if (g_is64){
            const long long* p = (const long long*)eidx;
            s = (int)p[e]; d = (int)p[EE + e];
        } else {
            const int* p = (const int*)eidx;
            s = p[e]; d = p[EE + e];
        }
        g_eidx[e] = make_int2(s, d);
    }
}

// ---------------- zero accumulators (vectorized) ----------------
__global__ void zero_kernel(){
    int i = blockIdx.x * blockDim.x + threadIdx.x;
    if (i < NN*DD/4) ((float4*)g_wV)[i] = make_float4(0.f,0.f,0.f,0.f);
    if (i < NN*HH/4) ((float4*)g_Z)[i]  = make_float4(0.f,0.f,0.f,0.f);
}

// ====== MMA tile compute, separate hi/lo B (node kernels, R11-proven) ====
__device__ __forceinline__ void gemm_tile_acc(
        const float* sA, const float* sBh, const float* sBl,
        int warp, int lane, float c[8][4]){
    const int gID = lane >> 2, tig = lane & 3;
    const int wr = warp * 16;
    #pragma unroll
    for (int k = 0; k < 8; k++){
        const float* ap = sA + (wr + gID)*ASTR + k*8 + tig;
        float a0f = ap[0], a1f = ap[8*ASTR], a2f = ap[4], a3f = ap[8*ASTR + 4];
        uint32_t ah[4], al[4];
        split_tf32(a0f, ah[0], al[0]);
        split_tf32(a1f, ah[1], al[1]);
        split_tf32(a2f, ah[2], al[2]);
        split_tf32(a3f, ah[3], al[3]);
        const int brow = k*8 + tig;
        #pragma unroll
        for (int nt = 0; nt < 8; nt++){
            const int bc = nt*8 + gID;
            uint32_t bh0 = __float_as_uint(sBh[brow*BSTR + bc]);
            uint32_t bh1 = __float_as_uint(sBh[(brow+4)*BSTR + bc]);
            uint32_t bl0 = __float_as_uint(sBl[brow*BSTR + bc]);
            uint32_t bl1 = __float_as_uint(sBl[(brow+4)*BSTR + bc]);
            mma8(c[nt], ah, bh0, bh1);   // hi*hi
            mma8(c[nt], ah, bl0, bl1);   // hi*lo
            mma8(c[nt], al, bh0, bh1);   // lo*hi
        }
    }
}

// ====== MMA tile compute, packed float2 B (edge kernel) ======
__device__ __forceinline__ void gemm_tile_acc_pk(
        const float* sA, const float2* sB2,
        int warp, int lane, float c[8][4]){
    const int gID = lane >> 2, tig = lane & 3;
    const int wr = warp * 16;
    #pragma unroll
    for (int k = 0; k < 8; k++){
        const float* ap = sA + (wr + gID)*ASTR + k*8 + tig;
        float a0f = ap[0], a1f = ap[8*ASTR], a2f = ap[4], a3f = ap[8*ASTR + 4];
        uint32_t ah[4], al[4];
        split_tf32(a0f, ah[0], al[0]);
        split_tf32(a1f, ah[1], al[1]);
        split_tf32(a2f, ah[2], al[2]);
        split_tf32(a3f, ah[3], al[3]);
        const int brow = k*8 + tig;
        #pragma unroll
        for (int nt = 0; nt < 8; nt++){
            const int bc = nt*8 + gID;
            float2 b0 = sB2[brow*B2STR + bc];        // {hi, lo} @ row brow
            float2 b1 = sB2[(brow+4)*B2STR + bc];    // {hi, lo} @ row brow+4
            mma8(c[nt], ah, __float_as_uint(b0.x), __float_as_uint(b1.x)); // hi*hi
            mma8(c[nt], ah, __float_as_uint(b0.y), __float_as_uint(b1.y)); // hi*lo
            mma8(c[nt], al, __float_as_uint(b0.x), __float_as_uint(b1.x)); // lo*hi
        }
    }
}

__device__ __forceinline__ void zero_c(float c[8][4]){
    #pragma unroll
    for (int nt = 0; nt < 8; nt++){ c[nt][0]=c[nt][1]=c[nt][2]=c[nt][3]=0.f; }
}

__device__ __forceinline__ void gemm_store(
        float* __restrict__ C, int m0, int M, int warp, int lane, float c[8][4]){
    const int gID = lane >> 2, tig = lane & 3;
    const int r0 = m0 + warp*16 + gID;
    const int r1 = r0 + 8;
    #pragma unroll
    for (int nt = 0; nt < 8; nt++){
        const int col = nt*8 + tig*2;
        if (r0 < M) *(float2*)&C[(size_t)r0*DD + col] = make_float2(c[nt][0], c[nt][1]);
        if (r1 < M) *(float2*)&C[(size_t)r1*DD + col] = make_float2(c[nt][2], c[nt][3]);
    }
}

// stage B (64x64) as separate hi/lo tf32 (node kernels)
__device__ __forceinline__ void stage_B_n(const float* __restrict__ B,
                                          float* sBh, float* sBl,
                                          int tid, int nthreads){
    for (int i = tid; i < 64*64; i += nthreads){
        int r = i >> 6, cc = i & 63;
        uint32_t h, l; split_tf32(B[i], h, l);
        sBh[r*BSTR + cc] = __uint_as_float(h);
        sBl[r*BSTR + cc] = __uint_as_float(l);
    }
}

// stage B (64x64) as packed float2{hi,lo} (edge kernel)
__device__ __forceinline__ void stage_B2(const float* __restrict__ B,
                                         float2* sB2, int tid, int nthreads){
    for (int i = tid; i < 64*64; i += nthreads){
        int r = i >> 6, cc = i & 63;
        uint32_t h, l; split_tf32(B[i], h, l);
        sB2[r*B2STR + cc] = make_float2(__uint_as_float(h), __uint_as_float(l));
    }
}

// register-resident LN epilogue over 64-col rows spread across a lane-quad
__device__ __forceinline__ void ln_epilogue(
        float c[8][4], int m0, int warp, int lane,
        const float* __restrict__ resid, const float* __restrict__ bias,
        const float* __restrict__ lg, const float* __restrict__ lb,
        float* __restrict__ out){
    const int gID = lane >> 2, tig = lane & 3;
    const int r0 = m0 + warp*16 + gID;
    const int r1 = r0 + 8;
    const int ra = (r0 < NN) ? r0 : NN-1;
    const int rb = (r1 < NN) ? r1 : NN-1;
    float s1a=0.f, s2a=0.f, s1b=0.f, s2b=0.f;
    #pragma unroll
    for (int nt = 0; nt < 8; nt++){
        const int col = nt*8 + tig*2;
        float2 bb = *(const float2*)&bias[col];
        float2 ha = *(const float2*)&resid[(size_t)ra*DD + col];
        float2 hb = *(const float2*)&resid[(size_t)rb*DD + col];
        c[nt][0] += bb.x + ha.x;  c[nt][1] += bb.y + ha.y;
        c[nt][2] += bb.x + hb.x;  c[nt][3] += bb.y + hb.y;
        s1a += c[nt][0] + c[nt][1];
        s2a += c[nt][0]*c[nt][0] + c[nt][1]*c[nt][1];
        s1b += c[nt][2] + c[nt][3];
        s2b += c[nt][2]*c[nt][2] + c[nt][3]*c[nt][3];
    }
    #pragma unroll
    for (int off = 1; off <= 2; off <<= 1){
        s1a += __shfl_xor_sync(0xffffffffu, s1a, off);
        s2a += __shfl_xor_sync(0xffffffffu, s2a, off);
        s1b += __shfl_xor_sync(0xffffffffu, s1b, off);
        s2b += __shfl_xor_sync(0xffffffffu, s2b, off);
    }
    const float mua = s1a*(1.0f/DD), vara = s2a*(1.0f/DD) - mua*mua;
    const float mub = s1b*(1.0f/DD), varb = s2b*(1.0f/DD) - mub*mub;
    const float inva = rsqrtf(vara + 1e-5f);
    const float invb = rsqrtf(varb + 1e-5f);
    #pragma unroll
    for (int nt = 0; nt < 8; nt++){
        const int col = nt*8 + tig*2;
        float2 gg = *(const float2*)&lg[col];
        float2 bb = *(const float2*)&lb[col];
        if (r0 < NN) *(float2*)&out[(size_t)r0*DD + col] =
            make_float2((c[nt][0]-mua)*inva*gg.x + bb.x,
                        (c[nt][1]-mua)*inva*gg.y + bb.y);
        if (r1 < NN) *(float2*)&out[(size_t)r1*DD + col] =
            make_float2((c[nt][2]-mub)*invb*gg.x + bb.x,
                        (c[nt][3]-mub)*invb*gg.y + bb.y);
    }
}

// ========== FUSED edge: 512 threads, 2x128-edge tiles, packed B ==========
// smem = 2*sA (69632 B) + sB2 (34816 B) = 104448 B -> 2 blocks/SM.
__global__ void __launch_bounds__(512, 2) edge_fused_kernel(
        const float* __restrict__ A,        // edge_attr
        const float* __restrict__ B){       // WE
    extern __shared__ float sm[];
    float*  sA  = sm;                       // 2 x (128 x ASTR)
    float2* sB2 = (float2*)(sm + 2*128*ASTR);
    const int tid = threadIdx.x;
    const int m0b = blockIdx.x * 256;       // EE % 256 == 0: no tail
    for (int i = tid; i < 256*64; i += 512){
        int r = i >> 6, cc = i & 63;
        sA[(r>>7)*(128*ASTR) + (r&127)*ASTR + cc] = A[(size_t)(m0b+r)*DD + cc];
    }
    stage_B2(B, sB2, tid, 512);
    __syncthreads();
    const int warp = tid >> 5, lane = tid & 31;
    const int tileid = warp >> 3;           // 0 or 1
    const int wl = warp & 7;
    float* sAt = sA + tileid*(128*ASTR);
    float c[8][4];
    zero_c(c);
    gemm_tile_acc_pk(sAt, sB2, wl, lane, c);
    __syncthreads();   // done reading edge_attr; safe to overwrite with Eh
    {
        const int gID = lane >> 2, tig = lane & 3;
        const int r0 = wl*16 + gID;
        const int r1 = r0 + 8;
        #pragma unroll
        for (int nt = 0; nt < 8; nt++){
            const int col = nt*8 + tig*2;
            *(float2*)&sAt[r0*ASTR + col] = make_float2(c[nt][0], c[nt][1]);
            *(float2*)&sAt[r1*ASTR + col] = make_float2(c[nt][2], c[nt][3]);
        }
    }
    __syncthreads();
    // ---- epilogue: each 256-thread half handles its tile's 128 edges ----
    const int ltid = tid & 255;
    const int t  = ltid & 15;
    const int g  = ltid >> 4;               // 0..15
    const int t4 = t * 4;
    const int m0 = m0b + tileid*128;
    int srcs[8], dsts[8];
    #pragma unroll
    for (int it = 0; it < 8; it++){
        int2 sd = g_eidx[m0 + it*16 + g];
        srcs[it] = sd.x; dsts[it] = sd.y;
    }
    #pragma unroll
    for (int it = 0; it < 8; it++){
        const int le  = it*16 + g;
        const int src = srcs[it], dst = dsts[it];
        float4 eh = *(const float4*)&sAt[le*ASTR + t4];
        float4 kk = *(const float4*)(g_K + (size_t)src*DD + t4);
        float4 qq = *(const float4*)(g_Q + (size_t)dst*DD + t4);
        float4 vv = *(const float4*)(g_V + (size_t)src*DD + t4);
        float s = kk.x*qq.x*eh.x + kk.y*qq.y*eh.y + kk.z*qq.z*eh.z + kk.w*qq.w*eh.w;
        s += __shfl_xor_sync(0xffffffffu, s, 1);
        s += __shfl_xor_sync(0xffffffffu, s, 2);
        s *= 0.25f;                        // 1/sqrt(16)
        s  = fminf(5.0f, fmaxf(-5.0f, s));
        float sc = expf(s);
        float* wb = g_wV + (size_t)dst*DD + t4;
        asm volatile("red.global.add.v4.f32 [%0], {%1, %2, %3, %4};"
                     :: "l"(wb), "f"(vv.x*sc), "f"(vv.y*sc), "f"(vv.z*sc), "f"(vv.w*sc)
                     : "memory");
        if ((t & 3) == 0){
            asm volatile("red.global.add.f32 [%0], %1;"
                         :: "l"(g_Z + (size_t)dst*HH + (t >> 2)), "f"(sc)
                         : "memory");
        }
    }
}

// ========== Q,K,V: 256 threads (R11-proven), loop over 3 weights ==========
__global__ void __launch_bounds__(256) qkv_mma_kernel(
        const float* __restrict__ A,
        const float* __restrict__ WQ, const float* __restrict__ WK,
        const float* __restrict__ WV, int M){
    extern __shared__ float sm[];
    float* sA  = sm;
    float* sBh = sm + 128*ASTR;
    float* sBl = sBh + 64*BSTR;
    const int tid = threadIdx.x;
    const int m0 = blockIdx.x * 128;
    for (int i = tid; i < 128*64; i += 256){
        int r = i >> 6, cc = i & 63;
        float v = (m0 + r < M) ? A[(size_t)(m0+r)*DD + cc] : 0.f;
        sA[r*ASTR + cc] = v;
    }
    const int warp = tid >> 5, lane = tid & 31;
    #pragma unroll
    for (int w = 0; w < 3; w++){
        const float* B = (w == 0) ? WQ : (w == 1) ? WK : WV;
        float* C = (w == 0) ? g_Q : (w == 1) ? g_K : g_V;
        __syncthreads();
        stage_B_n(B, sBh, sBl, tid, 256);
        __syncthreads();
        float c[8][4];
        zero_c(c);
        gemm_tile_acc(sA, sBh, sBl, warp, lane, c);
        gemm_store(C, m0, M, warp, lane, c);
    }
}

// ---- combine: h_attn = wV/Z; h1 = LN(h + h_attn@WO + bO), 256 thr ----
__global__ void __launch_bounds__(256) combine_mma_kernel(
        const float* __restrict__ h_in,
        const float* __restrict__ WO,
        const float* __restrict__ bO,
        const float* __restrict__ lg,
        const float* __restrict__ lb){
    extern __shared__ float sm[];
    float* sA  = sm;
    float* sBh = sm + 128*ASTR;
    float* sBl = sBh + 64*BSTR;
    const int tid = threadIdx.x;
    const int m0 = blockIdx.x * 128;
    for (int i = tid; i < 128*64; i += 256){
        int r = i >> 6, cc = i & 63;
        int n = m0 + r; if (n >= NN) n = NN-1;
        float z = g_Z[n*HH + (cc >> 4)];
        sA[r*ASTR + cc] = g_wV[(size_t)n*DD + cc] / (z + 1e-6f);
    }
    stage_B_n(WO, sBh, sBl, tid, 256);
    __syncthreads();
    const int warp = tid >> 5, lane = tid & 31;
    float c[8][4];
    zero_c(c);
    gemm_tile_acc(sA, sBh, sBl, warp, lane, c);
    ln_epilogue(c, m0, warp, lane, h_in, bO, lg, lb, g_h1);
}

// ---- FFN fc1: u = relu(h1@W1 + b1), 256 thr, two 64-col halves ----
__global__ void __launch_bounds__(256) ffn1_mma_kernel(
        const float* __restrict__ W1,
        const float* __restrict__ b1){
    extern __shared__ float sm[];
    float* sA  = sm;
    float* sBh = sm + 128*ASTR;
    float* sBl = sBh + 64*BSTR;
    const int tid = threadIdx.x;
    const int m0 = blockIdx.x * 128;
    for (int i = tid; i < 128*64; i += 256){
        int r = i >> 6, cc = i & 63;
        int n = m0 + r; if (n >= NN) n = NN-1;
        sA[r*ASTR + cc] = g_h1[(size_t)n*DD + cc];
    }
    const int warp = tid >> 5, lane = tid & 31;
    const int gID = lane >> 2, tig = lane & 3;
    #pragma unroll
    for (int w = 0; w < 2; w++){
        __syncthreads();
        for (int i = tid; i < 64*64; i += 256){
            int r = i >> 6, cc = i & 63;
            uint32_t h, l; split_tf32(W1[r*FF + w*64 + cc], h, l);
            sBh[r*BSTR + cc] = __uint_as_float(h);
            sBl[r*BSTR + cc] = __uint_as_float(l);
        }
        __syncthreads();
        float c[8][4];
        zero_c(c);
        gemm_tile_acc(sA, sBh, sBl, warp, lane, c);
        const int r0 = m0 + warp*16 + gID;
        const int r1 = r0 + 8;
        #pragma unroll
        for (int nt = 0; nt < 8; nt++){
            const int col = w*64 + nt*8 + tig*2;
            float2 bb = *(const float2*)&b1[col];
            if (r0 < NN) *(float2*)&g_u[(size_t)r0*FF + col] =
                make_float2(fmaxf(c[nt][0]+bb.x, 0.f), fmaxf(c[nt][1]+bb.y, 0.f));
            if (r1 < NN) *(float2*)&g_u[(size_t)r1*FF + col] =
                make_float2(fmaxf(c[nt][2]+bb.x, 0.f), fmaxf(c[nt][3]+bb.y, 0.f));
        }
    }
}

// ---- FFN fc2 + residual + LN2: 256 thr, k=128 via two 64-k chunks ----
__global__ void __launch_bounds__(256) ffn2_mma_kernel(
        const float* __restrict__ W2,
        const float* __restrict__ b2,
        const float* __restrict__ lg,
        const float* __restrict__ lb,
        float* __restrict__ outp){
    extern __shared__ float sm[];
    float* sA  = sm;
    float* sBh = sm + 128*ASTR;
    float* sBl = sBh + 64*BSTR;
    const int tid = threadIdx.x;
    const int m0 = blockIdx.x * 128;
    const int warp = tid >> 5, lane = tid & 31;
    float c[8][4];
    zero_c(c);
    #pragma unroll
    for (int kc = 0; kc < 2; kc++){
        __syncthreads();   // protect prior chunk's smem reads
        for (int i = tid; i < 128*64; i += 256){
            int r = i >> 6, cc = i & 63;
            int n = m0 + r; if (n >= NN) n = NN-1;
            sA[r*ASTR + cc] = g_u[(size_t)n*FF + kc*64 + cc];
        }
        for (int i = tid; i < 64*64; i += 256){
            int r = i >> 6, cc = i & 63;
            uint32_t h, l; split_tf32(W2[(kc*64 + r)*DD + cc], h, l);
            sBh[r*BSTR + cc] = __uint_as_float(h);
            sBl[r*BSTR + cc] = __uint_as_float(l);
        }
        __syncthreads();
        gemm_tile_acc(sA, sBh, sBl, warp, lane, c);
    }
    ln_epilogue(c, m0, warp, lane, g_h1, b2, lg, lb, outp);
}

// ---------------- host launcher ----------------
extern "C" void kernel_launch(void* const* d_in, const int* in_sizes, int n_in,
                              void* d_out, int out_size){
    const float* x   = (const float*)d_in[0];
    const float* ea  = (const float*)d_in[1];
    const void*  ei  = d_in[2];
    const float* WQ  = (const float*)d_in[3];
    const float* WK  = (const float*)d_in[4];
    const float* WE  = (const float*)d_in[5];
    const float* WV  = (const float*)d_in[6];
    const float* WO  = (const float*)d_in[7];
    const float* bO  = (const float*)d_in[8];
    const float* g1  = (const float*)d_in[9];
    const float* b1n = (const float*)d_in[10];
    const float* W1  = (const float*)d_in[11];
    const float* b1  = (const float*)d_in[12];
    const float* W2  = (const float*)d_in[13];
    const float* b2  = (const float*)d_in[14];
    const float* g2  = (const float*)d_in[15];
    const float* b2n = (const float*)d_in[16];
    float* outp = (float*)d_out;

    float* p_h = nullptr;
    cudaGetSymbolAddress((void**)&p_h, g_h);

    const int gemm_smem = (128*ASTR + 2*64*BSTR) * (int)sizeof(float);   // 71680 B
    const int edge_smem = 2*128*ASTR*4 + 64*B2STR*8;                     // 104448 B
    cudaFuncSetAttribute(edge_fused_kernel,
                         cudaFuncAttributeMaxDynamicSharedMemorySize, edge_smem);
    cudaFuncSetAttribute(qkv_mma_kernel,
                         cudaFuncAttributeMaxDynamicSharedMemorySize, gemm_smem);
    cudaFuncSetAttribute(combine_mma_kernel,
                         cudaFuncAttributeMaxDynamicSharedMemorySize, gemm_smem);
    cudaFuncSetAttribute(ffn1_mma_kernel,
                         cudaFuncAttributeMaxDynamicSharedMemorySize, gemm_smem);
    cudaFuncSetAttribute(ffn2_mma_kernel,
                         cudaFuncAttributeMaxDynamicSharedMemorySize, gemm_smem);

    detect_idx_kernel<<<1, 1>>>((const long long*)ei);
    convert_idx_kernel<<<(EE + 255)/256, 256>>>(ei);

    const int edge_blocks = EE / 256;          // 3125 (exact)
    const int node_blocks = (NN + 127) / 128;  // 391

    for (int l = 0; l < LL; l++){
        const float* hin  = (l == 0) ? x : (const float*)p_h;
        float*       hout = (l == LL-1) ? outp : p_h;
        zero_kernel<<<(NN*DD/4 + 255)/256, 256>>>();
        qkv_mma_kernel<<<node_blocks, 256, gemm_smem>>>(
            hin, WQ + l*DD*DD, WK + l*DD*DD, WV + l*DD*DD, NN);
        edge_fused_kernel<<<edge_blocks, 512, edge_smem>>>(
            ea, WE + l*DD*DD);
        combine_mma_kernel<<<node_blocks, 256, gemm_smem>>>(
            hin, WO + l*DD*DD, bO + l*DD, g1 + l*DD, b1n + l*DD);
        ffn1_mma_kernel<<<node_blocks, 256, gemm_smem>>>(
            W1 + l*DD*FF, b1 + l*FF);
        ffn2_mma_kernel<<<node_blocks, 256, gemm_smem>>>(
            W2 + l*FF*DD, b2 + l*DD, g2 + l*DD, b2n + l*DD, hout);
    }
}

// round 15
// speedup vs baseline: 1.1290x; 1.0289x over previous
#include <cuda_runtime.h>
#include <cstdint>

#define NN 50000
#define EE 800000
#define DD 64
#define HH 4
#define FF 128
#define LL 2

#define ASTR 68
#define BSTR 72

// ---------------- device scratch (static, no allocation) ----------------
__device__ float g_Q[NN*DD];
__device__ float g_K[NN*DD];
__device__ float g_V[NN*DD];
__device__ float g_wV[NN*DD];
__device__ float g_Z[NN*HH];
__device__ float g_h[NN*DD];    // inter-layer h
__device__ float g_h1[NN*DD];   // post-LN1
__device__ float g_u[NN*FF];    // FFN hidden
__device__ int2  g_eidx[EE];    // packed (src,dst) int32
__device__ int   g_is64;

// ---------------- tf32 helpers ----------------
__device__ __forceinline__ void split_tf32(float x, uint32_t& hi, uint32_t& lo){
    asm("cvt.rna.tf32.f32 %0, %1;" : "=r"(hi) : "f"(x));
    float r = x - __uint_as_float(hi);
    asm("cvt.rna.tf32.f32 %0, %1;" : "=r"(lo) : "f"(r));
}
__device__ __forceinline__ void mma8(float* c, const uint32_t* a, uint32_t b0, uint32_t b1){
    asm volatile(
      "mma.sync.aligned.m16n8k8.row.col.f32.tf32.tf32.f32 "
      "{%0,%1,%2,%3}, {%4,%5,%6,%7}, {%8,%9}, {%0,%1,%2,%3};"
      : "+f"(c[0]), "+f"(c[1]), "+f"(c[2]), "+f"(c[3])
      : "r"(a[0]), "r"(a[1]), "r"(a[2]), "r"(a[3]), "r"(b0), "r"(b1));
}

// ---------------- index dtype detection (int64 vs int32) ----------------
__global__ void detect_idx_kernel(const long long* __restrict__ idx){
    if (blockIdx.x == 0 && threadIdx.x == 0){
        int ok = 1;
        #pragma unroll
        for (int i = 0; i < 16; i++){
            long long v = idx[i];
            if (v < 0 || v >= NN) ok = 0;
        }
        g_is64 = ok;
    }
}

// ---------------- index conversion to packed int2 (once per launch) ------
__global__ void convert_idx_kernel(const void* __restrict__ eidx){
    int e = blockIdx.x * 256 + threadIdx.x;
    if (e < EE){
        int s, d;
        if (g_is64){
            const long long* p = (const long long*)eidx;
            s = (int)p[e]; d = (int)p[EE + e];
        } else {
            const int* p = (const int*)eidx;
            s = p[e]; d = p[EE + e];
        }
        g_eidx[e] = make_int2(s, d);
    }
}

// ---------------- zero accumulators (vectorized) ----------------
__global__ void zero_kernel(){
    int i = blockIdx.x * blockDim.x + threadIdx.x;
    if (i < NN*DD/4) ((float4*)g_wV)[i] = make_float4(0.f,0.f,0.f,0.f);
    if (i < NN*HH/4) ((float4*)g_Z)[i]  = make_float4(0.f,0.f,0.f,0.f);
}

// ====== MMA tile compute, 3xTF32 (node kernels — full precision) ======
__device__ __forceinline__ void gemm_tile_acc(
        const float* sA, const float* sBh, const float* sBl,
        int warp, int lane, float c[8][4]){
    const int gID = lane >> 2, tig = lane & 3;
    const int wr = warp * 16;
    #pragma unroll
    for (int k = 0; k < 8; k++){
        const float* ap = sA + (wr + gID)*ASTR + k*8 + tig;
        float a0f = ap[0], a1f = ap[8*ASTR], a2f = ap[4], a3f = ap[8*ASTR + 4];
        uint32_t ah[4], al[4];
        split_tf32(a0f, ah[0], al[0]);
        split_tf32(a1f, ah[1], al[1]);
        split_tf32(a2f, ah[2], al[2]);
        split_tf32(a3f, ah[3], al[3]);
        const int brow = k*8 + tig;
        #pragma unroll
        for (int nt = 0; nt < 8; nt++){
            const int bc = nt*8 + gID;
            uint32_t bh0 = __float_as_uint(sBh[brow*BSTR + bc]);
            uint32_t bh1 = __float_as_uint(sBh[(brow+4)*BSTR + bc]);
            uint32_t bl0 = __float_as_uint(sBl[brow*BSTR + bc]);
            uint32_t bl1 = __float_as_uint(sBl[(brow+4)*BSTR + bc]);
            mma8(c[nt], ah, bh0, bh1);   // hi*hi
            mma8(c[nt], ah, bl0, bl1);   // hi*lo
            mma8(c[nt], al, bh0, bh1);   // lo*hi
        }
    }
}

// ====== MMA tile compute, 2-term TF32 (edge kernel): a_hi*(b_hi+b_lo) ====
// Error = a_lo*b ~= 2^-11 relative per product; no A lo-split needed.
__device__ __forceinline__ void gemm_tile_acc_2t(
        const float* sA, const float* sBh, const float* sBl,
        int warp, int lane, float c[8][4]){
    const int gID = lane >> 2, tig = lane & 3;
    const int wr = warp * 16;
    #pragma unroll
    for (int k = 0; k < 8; k++){
        const float* ap = sA + (wr + gID)*ASTR + k*8 + tig;
        uint32_t ah[4];
        asm("cvt.rna.tf32.f32 %0, %1;" : "=r"(ah[0]) : "f"(ap[0]));
        asm("cvt.rna.tf32.f32 %0, %1;" : "=r"(ah[1]) : "f"(ap[8*ASTR]));
        asm("cvt.rna.tf32.f32 %0, %1;" : "=r"(ah[2]) : "f"(ap[4]));
        asm("cvt.rna.tf32.f32 %0, %1;" : "=r"(ah[3]) : "f"(ap[8*ASTR + 4]));
        const int brow = k*8 + tig;
        #pragma unroll
        for (int nt = 0; nt < 8; nt++){
            const int bc = nt*8 + gID;
            uint32_t bh0 = __float_as_uint(sBh[brow*BSTR + bc]);
            uint32_t bh1 = __float_as_uint(sBh[(brow+4)*BSTR + bc]);
            uint32_t bl0 = __float_as_uint(sBl[brow*BSTR + bc]);
            uint32_t bl1 = __float_as_uint(sBl[(brow+4)*BSTR + bc]);
            mma8(c[nt], ah, bh0, bh1);   // hi*hi
            mma8(c[nt], ah, bl0, bl1);   // hi*lo
        }
    }
}

__device__ __forceinline__ void zero_c(float c[8][4]){
    #pragma unroll
    for (int nt = 0; nt < 8; nt++){ c[nt][0]=c[nt][1]=c[nt][2]=c[nt][3]=0.f; }
}

__device__ __forceinline__ void gemm_store(
        float* __restrict__ C, int m0, int M, int warp, int lane, float c[8][4]){
    const int gID = lane >> 2, tig = lane & 3;
    const int r0 = m0 + warp*16 + gID;
    const int r1 = r0 + 8;
    #pragma unroll
    for (int nt = 0; nt < 8; nt++){
        const int col = nt*8 + tig*2;
        if (r0 < M) *(float2*)&C[(size_t)r0*DD + col] = make_float2(c[nt][0], c[nt][1]);
        if (r1 < M) *(float2*)&C[(size_t)r1*DD + col] = make_float2(c[nt][2], c[nt][3]);
    }
}

// stage B (64x64) as separate hi/lo tf32 into smem
__device__ __forceinline__ void stage_B_n(const float* __restrict__ B,
                                          float* sBh, float* sBl,
                                          int tid, int nthreads){
    for (int i = tid; i < 64*64; i += nthreads){
        int r = i >> 6, cc = i & 63;
        uint32_t h, l; split_tf32(B[i], h, l);
        sBh[r*BSTR + cc] = __uint_as_float(h);
        sBl[r*BSTR + cc] = __uint_as_float(l);
    }
}

// register-resident LN epilogue over 64-col rows spread across a lane-quad
__device__ __forceinline__ void ln_epilogue(
        float c[8][4], int m0, int warp, int lane,
        const float* __restrict__ resid, const float* __restrict__ bias,
        const float* __restrict__ lg, const float* __restrict__ lb,
        float* __restrict__ out){
    const int gID = lane >> 2, tig = lane & 3;
    const int r0 = m0 + warp*16 + gID;
    const int r1 = r0 + 8;
    const int ra = (r0 < NN) ? r0 : NN-1;
    const int rb = (r1 < NN) ? r1 : NN-1;
    float s1a=0.f, s2a=0.f, s1b=0.f, s2b=0.f;
    #pragma unroll
    for (int nt = 0; nt < 8; nt++){
        const int col = nt*8 + tig*2;
        float2 bb = *(const float2*)&bias[col];
        float2 ha = *(const float2*)&resid[(size_t)ra*DD + col];
        float2 hb = *(const float2*)&resid[(size_t)rb*DD + col];
        c[nt][0] += bb.x + ha.x;  c[nt][1] += bb.y + ha.y;
        c[nt][2] += bb.x + hb.x;  c[nt][3] += bb.y + hb.y;
        s1a += c[nt][0] + c[nt][1];
        s2a += c[nt][0]*c[nt][0] + c[nt][1]*c[nt][1];
        s1b += c[nt][2] + c[nt][3];
        s2b += c[nt][2]*c[nt][2] + c[nt][3]*c[nt][3];
    }
    #pragma unroll
    for (int off = 1; off <= 2; off <<= 1){
        s1a += __shfl_xor_sync(0xffffffffu, s1a, off);
        s2a += __shfl_xor_sync(0xffffffffu, s2a, off);
        s1b += __shfl_xor_sync(0xffffffffu, s1b, off);
        s2b += __shfl_xor_sync(0xffffffffu, s2b, off);
    }
    const float mua = s1a*(1.0f/DD), vara = s2a*(1.0f/DD) - mua*mua;
    const float mub = s1b*(1.0f/DD), varb = s2b*(1.0f/DD) - mub*mub;
    const float inva = rsqrtf(vara + 1e-5f);
    const float invb = rsqrtf(varb + 1e-5f);
    #pragma unroll
    for (int nt = 0; nt < 8; nt++){
        const int col = nt*8 + tig*2;
        float2 gg = *(const float2*)&lg[col];
        float2 bb = *(const float2*)&lb[col];
        if (r0 < NN) *(float2*)&out[(size_t)r0*DD + col] =
            make_float2((c[nt][0]-mua)*inva*gg.x + bb.x,
                        (c[nt][1]-mua)*inva*gg.y + bb.y);
        if (r1 < NN) *(float2*)&out[(size_t)r1*DD + col] =
            make_float2((c[nt][2]-mub)*invb*gg.x + bb.x,
                        (c[nt][3]-mub)*invb*gg.y + bb.y);
    }
}

// ========== FUSED edge: 512 threads, 2x128-edge tiles, 2-term TF32 ==========
// smem = 2*sA (69632 B) + sBh/sBl (36864 B) = 106496 B -> 2 blocks/SM.
__global__ void __launch_bounds__(512, 2) edge_fused_kernel(
        const float* __restrict__ A,        // edge_attr
        const float* __restrict__ B){       // WE
    extern __shared__ float sm[];
    float* sA  = sm;                        // 2 x (128 x ASTR)
    float* sBh = sm + 2*128*ASTR;           // 64 x BSTR
    float* sBl = sBh + 64*BSTR;
    const int tid = threadIdx.x;
    const int m0b = blockIdx.x * 256;       // EE % 256 == 0: no tail
    for (int i = tid; i < 256*64; i += 512){
        int r = i >> 6, cc = i & 63;
        sA[(r>>7)*(128*ASTR) + (r&127)*ASTR + cc] = A[(size_t)(m0b+r)*DD + cc];
    }
    stage_B_n(B, sBh, sBl, tid, 512);
    __syncthreads();
    const int warp = tid >> 5, lane = tid & 31;
    const int tileid = warp >> 3;           // 0 or 1
    const int wl = warp & 7;
    float* sAt = sA + tileid*(128*ASTR);
    float c[8][4];
    zero_c(c);
    gemm_tile_acc_2t(sAt, sBh, sBl, wl, lane, c);
    __syncthreads();   // done reading edge_attr; safe to overwrite with Eh
    {
        const int gID = lane >> 2, tig = lane & 3;
        const int r0 = wl*16 + gID;
        const int r1 = r0 + 8;
        #pragma unroll
        for (int nt = 0; nt < 8; nt++){
            const int col = nt*8 + tig*2;
            *(float2*)&sAt[r0*ASTR + col] = make_float2(c[nt][0], c[nt][1]);
            *(float2*)&sAt[r1*ASTR + col] = make_float2(c[nt][2], c[nt][3]);
        }
    }
    __syncthreads();
    // ---- epilogue: each 256-thread half handles its tile's 128 edges ----
    const int ltid = tid & 255;
    const int t  = ltid & 15;
    const int g  = ltid >> 4;               // 0..15
    const int t4 = t * 4;
    const int m0 = m0b + tileid*128;
    int srcs[8], dsts[8];
    #pragma unroll
    for (int it = 0; it < 8; it++){
        int2 sd = g_eidx[m0 + it*16 + g];
        srcs[it] = sd.x; dsts[it] = sd.y;
    }
    #pragma unroll
    for (int it = 0; it < 8; it++){
        const int le  = it*16 + g;
        const int src = srcs[it], dst = dsts[it];
        float4 eh = *(const float4*)&sAt[le*ASTR + t4];
        float4 kk = *(const float4*)(g_K + (size_t)src*DD + t4);
        float4 qq = *(const float4*)(g_Q + (size_t)dst*DD + t4);
        float4 vv = *(const float4*)(g_V + (size_t)src*DD + t4);
        float s = kk.x*qq.x*eh.x + kk.y*qq.y*eh.y + kk.z*qq.z*eh.z + kk.w*qq.w*eh.w;
        s += __shfl_xor_sync(0xffffffffu, s, 1);
        s += __shfl_xor_sync(0xffffffffu, s, 2);
        s *= 0.25f;                        // 1/sqrt(16)
        s  = fminf(5.0f, fmaxf(-5.0f, s));
        float sc = expf(s);
        float* wb = g_wV + (size_t)dst*DD + t4;
        asm volatile("red.global.add.v4.f32 [%0], {%1, %2, %3, %4};"
                     :: "l"(wb), "f"(vv.x*sc), "f"(vv.y*sc), "f"(vv.z*sc), "f"(vv.w*sc)
                     : "memory");
        if ((t & 3) == 0){
            asm volatile("red.global.add.f32 [%0], %1;"
                         :: "l"(g_Z + (size_t)dst*HH + (t >> 2)), "f"(sc)
                         : "memory");
        }
    }
}

// ========== Q,K,V: 256 threads (R11-proven), loop over 3 weights ==========
__global__ void __launch_bounds__(256) qkv_mma_kernel(
        const float* __restrict__ A,
        const float* __restrict__ WQ, const float* __restrict__ WK,
        const float* __restrict__ WV, int M){
    extern __shared__ float sm[];
    float* sA  = sm;
    float* sBh = sm + 128*ASTR;
    float* sBl = sBh + 64*BSTR;
    const int tid = threadIdx.x;
    const int m0 = blockIdx.x * 128;
    for (int i = tid; i < 128*64; i += 256){
        int r = i >> 6, cc = i & 63;
        float v = (m0 + r < M) ? A[(size_t)(m0+r)*DD + cc] : 0.f;
        sA[r*ASTR + cc] = v;
    }
    const int warp = tid >> 5, lane = tid & 31;
    #pragma unroll
    for (int w = 0; w < 3; w++){
        const float* B = (w == 0) ? WQ : (w == 1) ? WK : WV;
        float* C = (w == 0) ? g_Q : (w == 1) ? g_K : g_V;
        __syncthreads();
        stage_B_n(B, sBh, sBl, tid, 256);
        __syncthreads();
        float c[8][4];
        zero_c(c);
        gemm_tile_acc(sA, sBh, sBl, warp, lane, c);
        gemm_store(C, m0, M, warp, lane, c);
    }
}

// ---- combine: h_attn = wV/Z; h1 = LN(h + h_attn@WO + bO), 256 thr ----
__global__ void __launch_bounds__(256) combine_mma_kernel(
        const float* __restrict__ h_in,
        const float* __restrict__ WO,
        const float* __restrict__ bO,
        const float* __restrict__ lg,
        const float* __restrict__ lb){
    extern __shared__ float sm[];
    float* sA  = sm;
    float* sBh = sm + 128*ASTR;
    float* sBl = sBh + 64*BSTR;
    const int tid = threadIdx.x;
    const int m0 = blockIdx.x * 128;
    for (int i = tid; i < 128*64; i += 256){
        int r = i >> 6, cc = i & 63;
        int n = m0 + r; if (n >= NN) n = NN-1;
        float z = g_Z[n*HH + (cc >> 4)];
        sA[r*ASTR + cc] = g_wV[(size_t)n*DD + cc] / (z + 1e-6f);
    }
    stage_B_n(WO, sBh, sBl, tid, 256);
    __syncthreads();
    const int warp = tid >> 5, lane = tid & 31;
    float c[8][4];
    zero_c(c);
    gemm_tile_acc(sA, sBh, sBl, warp, lane, c);
    ln_epilogue(c, m0, warp, lane, h_in, bO, lg, lb, g_h1);
}

// ---- FFN fc1: u = relu(h1@W1 + b1), 256 thr, two 64-col halves ----
__global__ void __launch_bounds__(256) ffn1_mma_kernel(
        const float* __restrict__ W1,
        const float* __restrict__ b1){
    extern __shared__ float sm[];
    float* sA  = sm;
    float* sBh = sm + 128*ASTR;
    float* sBl = sBh + 64*BSTR;
    const int tid = threadIdx.x;
    const int m0 = blockIdx.x * 128;
    for (int i = tid; i < 128*64; i += 256){
        int r = i >> 6, cc = i & 63;
        int n = m0 + r; if (n >= NN) n = NN-1;
        sA[r*ASTR + cc] = g_h1[(size_t)n*DD + cc];
    }
    const int warp = tid >> 5, lane = tid & 31;
    const int gID = lane >> 2, tig = lane & 3;
    #pragma unroll
    for (int w = 0; w < 2; w++){
        __syncthreads();
        for (int i = tid; i < 64*64; i += 256){
            int r = i >> 6, cc = i & 63;
            uint32_t h, l; split_tf32(W1[r*FF + w*64 + cc], h, l);
            sBh[r*BSTR + cc] = __uint_as_float(h);
            sBl[r*BSTR + cc] = __uint_as_float(l);
        }
        __syncthreads();
        float c[8][4];
        zero_c(c);
        gemm_tile_acc(sA, sBh, sBl, warp, lane, c);
        const int r0 = m0 + warp*16 + gID;
        const int r1 = r0 + 8;
        #pragma unroll
        for (int nt = 0; nt < 8; nt++){
            const int col = w*64 + nt*8 + tig*2;
            float2 bb = *(const float2*)&b1[col];
            if (r0 < NN) *(float2*)&g_u[(size_t)r0*FF + col] =
                make_float2(fmaxf(c[nt][0]+bb.x, 0.f), fmaxf(c[nt][1]+bb.y, 0.f));
            if (r1 < NN) *(float2*)&g_u[(size_t)r1*FF + col] =
                make_float2(fmaxf(c[nt][2]+bb.x, 0.f), fmaxf(c[nt][3]+bb.y, 0.f));
        }
    }
}

// ---- FFN fc2 + residual + LN2: 256 thr, k=128 via two 64-k chunks ----
__global__ void __launch_bounds__(256) ffn2_mma_kernel(
        const float* __restrict__ W2,
        const float* __restrict__ b2,
        const float* __restrict__ lg,
        const float* __restrict__ lb,
        float* __restrict__ outp){
    extern __shared__ float sm[];
    float* sA  = sm;
    float* sBh = sm + 128*ASTR;
    float* sBl = sBh + 64*BSTR;
    const int tid = threadIdx.x;
    const int m0 = blockIdx.x * 128;
    const int warp = tid >> 5, lane = tid & 31;
    float c[8][4];
    zero_c(c);
    #pragma unroll
    for (int kc = 0; kc < 2; kc++){
        __syncthreads();   // protect prior chunk's smem reads
        for (int i = tid; i < 128*64; i += 256){
            int r = i >> 6, cc = i & 63;
            int n = m0 + r; if (n >= NN) n = NN-1;
            sA[r*ASTR + cc] = g_u[(size_t)n*FF + kc*64 + cc];
        }
        for (int i = tid; i < 64*64; i += 256){
            int r = i >> 6, cc = i & 63;
            uint32_t h, l; split_tf32(W2[(kc*64 + r)*DD + cc], h, l);
            sBh[r*BSTR + cc] = __uint_as_float(h);
            sBl[r*BSTR + cc] = __uint_as_float(l);
        }
        __syncthreads();
        gemm_tile_acc(sA, sBh, sBl, warp, lane, c);
    }
    ln_epilogue(c, m0, warp, lane, g_h1, b2, lg, lb, outp);
}

// ---------------- host launcher ----------------
extern "C" void kernel_launch(void* const* d_in, const int* in_sizes, int n_in,
                              void* d_out, int out_size){
    const float* x   = (const float*)d_in[0];
    const float* ea  = (const float*)d_in[1];
    const void*  ei  = d_in[2];
    const float* WQ  = (const float*)d_in[3];
    const float* WK  = (const float*)d_in[4];
    const float* WE  = (const float*)d_in[5];
    const float* WV  = (const float*)d_in[6];
    const float* WO  = (const float*)d_in[7];
    const float* bO  = (const float*)d_in[8];
    const float* g1  = (const float*)d_in[9];
    const float* b1n = (const float*)d_in[10];
    const float* W1  = (const float*)d_in[11];
    const float* b1  = (const float*)d_in[12];
    const float* W2  = (const float*)d_in[13];
    const float* b2  = (const float*)d_in[14];
    const float* g2  = (const float*)d_in[15];
    const float* b2n = (const float*)d_in[16];
    float* outp = (float*)d_out;

    float* p_h = nullptr;
    cudaGetSymbolAddress((void**)&p_h, g_h);

    const int gemm_smem = (128*ASTR + 2*64*BSTR) * (int)sizeof(float);   // 71680 B
    const int edge_smem = (2*128*ASTR + 2*64*BSTR) * (int)sizeof(float); // 106496 B
    cudaFuncSetAttribute(edge_fused_kernel,
                         cudaFuncAttributeMaxDynamicSharedMemorySize, edge_smem);
    cudaFuncSetAttribute(qkv_mma_kernel,
                         cudaFuncAttributeMaxDynamicSharedMemorySize, gemm_smem);
    cudaFuncSetAttribute(combine_mma_kernel,
                         cudaFuncAttributeMaxDynamicSharedMemorySize, gemm_smem);
    cudaFuncSetAttribute(ffn1_mma_kernel,
                         cudaFuncAttributeMaxDynamicSharedMemorySize, gemm_smem);
    cudaFuncSetAttribute(ffn2_mma_kernel,
                         cudaFuncAttributeMaxDynamicSharedMemorySize, gemm_smem);

    detect_idx_kernel<<<1, 1>>>((const long long*)ei);
    convert_idx_kernel<<<(EE + 255)/256, 256>>>(ei);

    const int edge_blocks = EE / 256;          // 3125 (exact)
    const int node_blocks = (NN + 127) / 128;  // 391

    for (int l = 0; l < LL; l++){
        const float* hin  = (l == 0) ? x : (const float*)p_h;
        float*       hout = (l == LL-1) ? outp : p_h;
        zero_kernel<<<(NN*DD/4 + 255)/256, 256>>>();
        qkv_mma_kernel<<<node_blocks, 256, gemm_smem>>>(
            hin, WQ + l*DD*DD, WK + l*DD*DD, WV + l*DD*DD, NN);
        edge_fused_kernel<<<edge_blocks, 512, edge_smem>>>(
            ea, WE + l*DD*DD);
        combine_mma_kernel<<<node_blocks, 256, gemm_smem>>>(
            hin, WO + l*DD*DD, bO + l*DD, g1 + l*DD, b1n + l*DD);
        ffn1_mma_kernel<<<node_blocks, 256, gemm_smem>>>(
            W1 + l*DD*FF, b1 + l*FF);
        ffn2_mma_kernel<<<node_blocks, 256, gemm_smem>>>(
            W2 + l*FF*DD, b2 + l*DD, g2 + l*DD, b2n + l*DD, hout);
    }
}